// round 1
// baseline (speedup 1.0000x reference)
#include <cuda_runtime.h>
#include <cuda_bf16.h>
#include <cstdint>

// Problem constants
#define BATCH 8
#define SEQ   4096
#define DIM   512
#define HEADS 8
#define DH    64
#define INNER 512          // HEADS*DH
#define QKV_COLS 1536      // 3*INNER
#define ROWS  (BATCH*SEQ)  // 32768
#define EPS   1e-5f

// Scratch (device globals; no allocation allowed)
__device__ float g_qkv[(size_t)ROWS * QKV_COLS];   // 201 MB: q|k|v sections per row
__device__ float g_dots[BATCH * HEADS * DH * DH];  // 1 MB
__device__ float g_attn[(size_t)ROWS * INNER];     // 67 MB

// ---------------------------------------------------------------------------
// packed f32x2 helpers (Blackwell FFMA2 path, PTX-only)
// ---------------------------------------------------------------------------
__device__ __forceinline__ unsigned long long pack2(float lo, float hi) {
    unsigned long long r;
    asm("mov.b64 %0, {%1,%2};" : "=l"(r) : "f"(lo), "f"(hi));
    return r;
}
__device__ __forceinline__ void unpack2(unsigned long long v, float& lo, float& hi) {
    asm("mov.b64 {%0,%1}, %2;" : "=f"(lo), "=f"(hi) : "l"(v));
}
__device__ __forceinline__ void fma2(unsigned long long& acc, unsigned long long a, unsigned long long b) {
    asm("fma.rn.f32x2 %0, %1, %2, %0;" : "+l"(acc) : "l"(a), "l"(b));
}

// ---------------------------------------------------------------------------
// NT GEMM: C[m, j] = sum_k A[m,k] * B[j,k]  (+ optional bias[j])
// A: M x K row-major (K contiguous), B: Ncols x K row-major.
// 128x128 tile, BK=16, 256 threads, 8x8 per thread via f32x2 pairs.
// All dims divide evenly for this problem (no guards).
// ---------------------------------------------------------------------------
__device__ __forceinline__ void gemm_body(const float* __restrict__ A,
                                          const float* __restrict__ B,
                                          const float* __restrict__ bias,
                                          float* __restrict__ C,
                                          int Ncols, int K) {
    __shared__ float As[16][128];
    __shared__ float Bs[16][128];

    const int tid = threadIdx.x;
    const int bm = blockIdx.y * 128;
    const int bn = blockIdx.x * 128;

    const int lr = tid >> 2;          // 0..63
    const int lc = (tid & 3) * 4;     // 0,4,8,12
    const float* Ap = A + (size_t)(bm + lr) * K + lc;
    const float* Bp = B + (size_t)(bn + lr) * K + lc;

    const int tm = (tid >> 4) * 8;
    const int tn = (tid & 15) * 8;

    unsigned long long acc[8][4];
#pragma unroll
    for (int i = 0; i < 8; i++)
#pragma unroll
        for (int j = 0; j < 4; j++) acc[i][j] = 0ull;

    for (int k0 = 0; k0 < K; k0 += 16) {
        float4 a0 = *(const float4*)(Ap);
        float4 a1 = *(const float4*)(Ap + (size_t)64 * K);
        float4 b0 = *(const float4*)(Bp);
        float4 b1 = *(const float4*)(Bp + (size_t)64 * K);
        Ap += 16; Bp += 16;

        __syncthreads();   // previous iter's compute done before overwrite
        As[lc + 0][lr] = a0.x; As[lc + 1][lr] = a0.y; As[lc + 2][lr] = a0.z; As[lc + 3][lr] = a0.w;
        As[lc + 0][lr + 64] = a1.x; As[lc + 1][lr + 64] = a1.y; As[lc + 2][lr + 64] = a1.z; As[lc + 3][lr + 64] = a1.w;
        Bs[lc + 0][lr] = b0.x; Bs[lc + 1][lr] = b0.y; Bs[lc + 2][lr] = b0.z; Bs[lc + 3][lr] = b0.w;
        Bs[lc + 0][lr + 64] = b1.x; Bs[lc + 1][lr + 64] = b1.y; Bs[lc + 2][lr + 64] = b1.z; Bs[lc + 3][lr + 64] = b1.w;
        __syncthreads();

#pragma unroll
        for (int kk = 0; kk < 16; kk++) {
            float4 av0 = *(const float4*)&As[kk][tm];
            float4 av1 = *(const float4*)&As[kk][tm + 4];
            float4 bv0 = *(const float4*)&Bs[kk][tn];
            float4 bv1 = *(const float4*)&Bs[kk][tn + 4];
            unsigned long long bp[4] = {pack2(bv0.x, bv0.y), pack2(bv0.z, bv0.w),
                                        pack2(bv1.x, bv1.y), pack2(bv1.z, bv1.w)};
            float aa[8] = {av0.x, av0.y, av0.z, av0.w, av1.x, av1.y, av1.z, av1.w};
#pragma unroll
            for (int i = 0; i < 8; i++) {
                unsigned long long ap = pack2(aa[i], aa[i]);
#pragma unroll
                for (int j = 0; j < 4; j++) fma2(acc[i][j], ap, bp[j]);
            }
        }
    }

#pragma unroll
    for (int i = 0; i < 8; i++) {
        size_t row = (size_t)(bm + tm + i) * Ncols;
#pragma unroll
        for (int j = 0; j < 4; j++) {
            float lo, hi;
            unpack2(acc[i][j], lo, hi);
            int col = bn + tn + 2 * j;
            if (bias) { lo += bias[col]; hi += bias[col + 1]; }
            C[row + col] = lo;
            C[row + col + 1] = hi;
        }
    }
}

__global__ __launch_bounds__(256) void gemm_qkv_kernel(const float* __restrict__ x,
                                                       const float* __restrict__ Wqkv) {
    gemm_body(x, Wqkv, nullptr, g_qkv, QKV_COLS, DIM);
}
__global__ __launch_bounds__(256) void gemm_out_kernel(const float* __restrict__ Wout,
                                                       const float* __restrict__ bout,
                                                       float* __restrict__ out) {
    gemm_body(g_attn, Wout, bout, out, DIM, INNER);
}

// ---------------------------------------------------------------------------
// LN(k,v over DH) + 2D RoPE(q,k) in-place on g_qkv. One warp per (b,n,h) row.
// elem j = lane (first 32, coord x) and lane+32 (last 32, coord y).
// rotate_half over each 32-half: rh[l] = (l<16 ? -t[l+16] : t[l-16]) = sgn*shfl_xor(t,16)
// theta = coord * 64 * 10000^{-(l&15)/16}
// ---------------------------------------------------------------------------
__device__ __forceinline__ float warp_sum(float v) {
#pragma unroll
    for (int o = 16; o > 0; o >>= 1) v += __shfl_xor_sync(0xffffffffu, v, o);
    return v;
}

__global__ __launch_bounds__(256) void ln_rope_kernel(const float* __restrict__ pos,
                                                      const float* __restrict__ gk,
                                                      const float* __restrict__ bk,
                                                      const float* __restrict__ gv,
                                                      const float* __restrict__ bv) {
    const int warp = threadIdx.x >> 5;
    const int lane = threadIdx.x & 31;
    const int r = blockIdx.x * 8 + warp;             // 0 .. B*N*H-1
    const int b = r >> 15;                           // / (SEQ*HEADS)
    const int rem = r & 32767;
    const int n = rem >> 3;
    const int h = rem & 7;

    float* qp = g_qkv + ((size_t)(b * SEQ + n)) * QKV_COLS + h * DH;
    float* kp = qp + INNER;
    float* vp = qp + 2 * INNER;

    float q0 = qp[lane], q1 = qp[lane + 32];
    float k0 = kp[lane], k1 = kp[lane + 32];
    float v0 = vp[lane], v1 = vp[lane + 32];

    // LayerNorm k
    float mu = warp_sum(k0 + k1) * (1.0f / 64.0f);
    float d0 = k0 - mu, d1 = k1 - mu;
    float var = warp_sum(d0 * d0 + d1 * d1) * (1.0f / 64.0f);
    float inv = rsqrtf(var + EPS);
    k0 = d0 * inv * gk[lane] + bk[lane];
    k1 = d1 * inv * gk[lane + 32] + bk[lane + 32];

    // LayerNorm v
    mu = warp_sum(v0 + v1) * (1.0f / 64.0f);
    d0 = v0 - mu; d1 = v1 - mu;
    var = warp_sum(d0 * d0 + d1 * d1) * (1.0f / 64.0f);
    inv = rsqrtf(var + EPS);
    v0 = d0 * inv * gv[lane] + bv[lane];
    v1 = d1 * inv * gv[lane + 32] + bv[lane + 32];

    // RoPE
    const float cx = pos[((size_t)(b * SEQ + n)) * 2 + 0];
    const float cy = pos[((size_t)(b * SEQ + n)) * 2 + 1];
    // invf = 10000^{-(lane&15)/16} = 2^{-(lane&15)/16 * log2(10000)}
    float invf = exp2f(-0.830482023721841f * (float)(lane & 15));
    float sx, cxs, sy, cys;
    sincosf(cx * 64.0f * invf, &sx, &cxs);
    sincosf(cy * 64.0f * invf, &sy, &cys);
    const float sgn = (lane < 16) ? -1.0f : 1.0f;

    float qr0 = q0 * cxs + sgn * __shfl_xor_sync(0xffffffffu, q0, 16) * sx;
    float qr1 = q1 * cys + sgn * __shfl_xor_sync(0xffffffffu, q1, 16) * sy;
    float kr0 = k0 * cxs + sgn * __shfl_xor_sync(0xffffffffu, k0, 16) * sx;
    float kr1 = k1 * cys + sgn * __shfl_xor_sync(0xffffffffu, k1, 16) * sy;

    qp[lane] = qr0; qp[lane + 32] = qr1;
    kp[lane] = kr0; kp[lane + 32] = kr1;
    vp[lane] = v0;  vp[lane + 32] = v1;
}

// ---------------------------------------------------------------------------
// zero g_dots
// ---------------------------------------------------------------------------
__global__ void zero_dots_kernel() {
    g_dots[blockIdx.x * blockDim.x + threadIdx.x] = 0.0f;
}

// ---------------------------------------------------------------------------
// dots[b,h,d,e] = sum_n k[b,h,n,d] * v[b,h,n,e]
// grid (64 bh, 16 chunks of 256 tokens). 256 threads, 4x4 outer-product tile
// per thread, 8 tokens staged in smem per inner pass. atomicAdd at end.
// ---------------------------------------------------------------------------
__global__ __launch_bounds__(256) void kv_dots_kernel() {
    __shared__ float ks[8][64];
    __shared__ float vs[8][64];

    const int bh = blockIdx.x;
    const int b = bh >> 3, h = bh & 7;
    const int n0 = blockIdx.y * 256;
    const int tid = threadIdx.x;
    const int d0 = (tid >> 4) * 4;
    const int e0 = (tid & 15) * 4;

    float acc[4][4];
#pragma unroll
    for (int i = 0; i < 4; i++)
#pragma unroll
        for (int j = 0; j < 4; j++) acc[i][j] = 0.0f;

    for (int t0 = 0; t0 < 256; t0 += 8) {
        __syncthreads();
        // stage 8 k-rows and 8 v-rows (512 floats each)
#pragma unroll
        for (int i = tid; i < 1024; i += 256) {
            int sel = i >> 9;            // 0: k, 1: v
            int ii = i & 511;
            int tt = ii >> 6;
            int d = ii & 63;
            size_t row = ((size_t)(b * SEQ + n0 + t0 + tt)) * QKV_COLS + h * DH;
            float val = g_qkv[row + (sel ? 2 * INNER : INNER) + d];
            if (sel) vs[tt][d] = val; else ks[tt][d] = val;
        }
        __syncthreads();
#pragma unroll
        for (int tt = 0; tt < 8; tt++) {
            float kv[4], vv[4];
#pragma unroll
            for (int i = 0; i < 4; i++) kv[i] = ks[tt][d0 + i];
#pragma unroll
            for (int j = 0; j < 4; j++) vv[j] = vs[tt][e0 + j];
#pragma unroll
            for (int i = 0; i < 4; i++)
#pragma unroll
                for (int j = 0; j < 4; j++) acc[i][j] += kv[i] * vv[j];
        }
    }

    float* dbase = g_dots + (size_t)bh * DH * DH;
#pragma unroll
    for (int i = 0; i < 4; i++)
#pragma unroll
        for (int j = 0; j < 4; j++)
            atomicAdd(&dbase[(d0 + i) * DH + (e0 + j)], acc[i][j]);
}

// ---------------------------------------------------------------------------
// attn[b,n,h*64+e] = (1/SEQ) * sum_d q[b,n,h,d] * dots[b,h,d,e]
// grid (64 bh, 32 chunks of 128 tokens), 256 threads = 8 warps.
// dots tile (pre-scaled) in smem; each warp streams its 16 tokens.
// ---------------------------------------------------------------------------
__global__ __launch_bounds__(256) void q_dots_kernel() {
    __shared__ float ds[DH * DH];       // 16 KB
    __shared__ float qrow[8][DH];       // 2 KB

    const int bh = blockIdx.x;
    const int b = bh >> 3, h = bh & 7;
    const int n0 = blockIdx.y * 128;
    const int tid = threadIdx.x;
    const int warp = tid >> 5;
    const int lane = tid & 31;

    for (int i = tid; i < DH * DH; i += 256)
        ds[i] = g_dots[(size_t)bh * DH * DH + i] * (1.0f / (float)SEQ);
    __syncthreads();

    for (int it = 0; it < 16; it++) {
        int n = n0 + warp * 16 + it;
        size_t row = ((size_t)(b * SEQ + n)) * QKV_COLS + h * DH;
        qrow[warp][lane] = g_qkv[row + lane];
        qrow[warp][lane + 32] = g_qkv[row + lane + 32];
        __syncwarp();
        float a0 = 0.0f, a1 = 0.0f;
#pragma unroll
        for (int d = 0; d < DH; d++) {
            float qd = qrow[warp][d];
            a0 += qd * ds[d * DH + lane];
            a1 += qd * ds[d * DH + lane + 32];
        }
        size_t orow = ((size_t)(b * SEQ + n)) * INNER + h * DH;
        g_attn[orow + lane] = a0;
        g_attn[orow + lane + 32] = a1;
        __syncwarp();
    }
}

// ---------------------------------------------------------------------------
// launch
// ---------------------------------------------------------------------------
extern "C" void kernel_launch(void* const* d_in, const int* in_sizes, int n_in,
                              void* d_out, int out_size) {
    const float* x    = (const float*)d_in[0];
    const float* pos  = (const float*)d_in[1];
    const float* Wqkv = (const float*)d_in[2];
    const float* gk   = (const float*)d_in[3];
    const float* bk   = (const float*)d_in[4];
    const float* gv   = (const float*)d_in[5];
    const float* bv   = (const float*)d_in[6];
    const float* Wout = (const float*)d_in[7];
    const float* bout = (const float*)d_in[8];
    float* out = (float*)d_out;

    // 1) qkv = x @ Wqkv^T  -> g_qkv
    gemm_qkv_kernel<<<dim3(QKV_COLS / 128, ROWS / 128), 256>>>(x, Wqkv);
    // 2) LN(k,v) + RoPE(q,k) in-place
    ln_rope_kernel<<<(BATCH * SEQ * HEADS) / 8, 256>>>(pos, gk, bk, gv, bv);
    // 3) dots = K^T V  (zero, then atomic accumulate)
    zero_dots_kernel<<<(BATCH * HEADS * DH * DH) / 256, 256>>>();
    kv_dots_kernel<<<dim3(BATCH * HEADS, SEQ / 256), 256>>>();
    // 4) attn = (Q @ dots) / N
    q_dots_kernel<<<dim3(BATCH * HEADS, SEQ / 128), 256>>>();
    // 5) out = attn @ Wout^T + bout
    gemm_out_kernel<<<dim3(DIM / 128, ROWS / 128), 256>>>(Wout, bout, out);
}

// round 3
// speedup vs baseline: 2.1825x; 2.1825x over previous
#include <cuda_runtime.h>
#include <cuda_bf16.h>
#include <cstdint>

// Problem constants
#define BATCH 8
#define SEQ   4096
#define DIM   512
#define HEADS 8
#define DH    64
#define INNER 512          // HEADS*DH
#define QKV_COLS 1536      // 3*INNER
#define ROWS  (BATCH*SEQ)  // 32768
#define EPS   1e-5f

// ---------------------------------------------------------------------------
// Scratch (device globals; no allocation allowed)
// ---------------------------------------------------------------------------
__device__ float g_qkv[(size_t)ROWS * QKV_COLS];            // 201 MB fp32 q|k|v
__device__ float g_dots[BATCH * HEADS * DH * DH];           // 1 MB
__device__ __nv_bfloat16 g_xh[(size_t)ROWS * DIM];          // 32 MB
__device__ __nv_bfloat16 g_xl[(size_t)ROWS * DIM];
__device__ __nv_bfloat16 g_wh[(size_t)QKV_COLS * DIM];      // 1.5 MB
__device__ __nv_bfloat16 g_wl[(size_t)QKV_COLS * DIM];
__device__ __nv_bfloat16 g_qh[(size_t)ROWS * INNER];        // 32 MB
__device__ __nv_bfloat16 g_ql[(size_t)ROWS * INNER];
__device__ __nv_bfloat16 g_mh[(size_t)BATCH * DIM * INNER]; // 4 MB
__device__ __nv_bfloat16 g_ml[(size_t)BATCH * DIM * INNER];

// ---------------------------------------------------------------------------
// mma.sync bf16 GEMM machinery (arch-agnostic PTX: works on sm_103 target)
// ---------------------------------------------------------------------------
#define BK 32
#define SROW 40                       // padded smem row stride (bf16 elems) -> 80B
#define MAT_BYTES (128 * SROW * 2)    // 10240 per operand tile
#define STAGE_BYTES (4 * MAT_BYTES)   // Ah|Al|Bh|Bl = 40960
#define GEMM_SMEM (2 * STAGE_BYTES)   // double buffered = 81920

__device__ __forceinline__ void cp16(uint32_t sdst, const void* gsrc) {
    asm volatile("cp.async.cg.shared.global [%0], [%1], 16;"
                 :: "r"(sdst), "l"(gsrc) : "memory");
}
__device__ __forceinline__ void cp_commit() {
    asm volatile("cp.async.commit_group;" ::: "memory");
}
template <int N> __device__ __forceinline__ void cp_wait() {
    asm volatile("cp.async.wait_group %0;" :: "n"(N) : "memory");
}
__device__ __forceinline__ void ldsm4(uint32_t* r, uint32_t a) {
    asm volatile("ldmatrix.sync.aligned.m8n8.x4.shared.b16 {%0,%1,%2,%3}, [%4];"
                 : "=r"(r[0]), "=r"(r[1]), "=r"(r[2]), "=r"(r[3]) : "r"(a));
}
__device__ __forceinline__ void ldsm2(uint32_t* r, uint32_t a) {
    asm volatile("ldmatrix.sync.aligned.m8n8.x2.shared.b16 {%0,%1}, [%2];"
                 : "=r"(r[0]), "=r"(r[1]) : "r"(a));
}
__device__ __forceinline__ void mma16816(float* c, const uint32_t* a, const uint32_t* b) {
    asm volatile(
        "mma.sync.aligned.m16n8k16.row.col.f32.bf16.bf16.f32 "
        "{%0,%1,%2,%3}, {%4,%5,%6,%7}, {%8,%9}, {%0,%1,%2,%3};"
        : "+f"(c[0]), "+f"(c[1]), "+f"(c[2]), "+f"(c[3])
        : "r"(a[0]), "r"(a[1]), "r"(a[2]), "r"(a[3]), "r"(b[0]), "r"(b[1]));
}

// Stage loader: 4 operand tiles of 128 rows x 32 bf16, source row stride 512.
__device__ __forceinline__ void stage_load(uint32_t sbase,
                                           const __nv_bfloat16* __restrict__ Ah,
                                           const __nv_bfloat16* __restrict__ Al,
                                           const __nv_bfloat16* __restrict__ Bh,
                                           const __nv_bfloat16* __restrict__ Bl,
                                           int k0, int tid) {
#pragma unroll
    for (int hh = 0; hh < 2; hh++) {
        int i = tid + hh * 256;               // 0..511
        int row = i >> 2, c8 = i & 3;
        uint32_t so = sbase + (uint32_t)(row * (SROW * 2) + c8 * 16);
        size_t go = (size_t)row * 512 + k0 + c8 * 8;
        cp16(so,                 Ah + go);
        cp16(so + MAT_BYTES,     Al + go);
        cp16(so + 2 * MAT_BYTES, Bh + go);
        cp16(so + 3 * MAT_BYTES, Bl + go);
    }
}

// C[128,128] = (Ah+Al)[128,512] @ (Bh+Bl)[128,512]^T, fp32 accum,
// 3-pass split (hi*hi + hi*lo + lo*hi). 256 threads, warp tile 64x32.
__device__ __forceinline__ void tc_gemm(const __nv_bfloat16* __restrict__ Ah,
                                        const __nv_bfloat16* __restrict__ Al,
                                        const __nv_bfloat16* __restrict__ Bh,
                                        const __nv_bfloat16* __restrict__ Bl,
                                        const float* __restrict__ bias,
                                        float* __restrict__ C, int ldc) {
    extern __shared__ char sm[];
    const uint32_t sbase = (uint32_t)__cvta_generic_to_shared(sm);
    const int tid = threadIdx.x;
    const int lane = tid & 31;
    const int wid = tid >> 5;
    const int wm = wid >> 2;          // 0..1 (64 rows each)
    const int wn = wid & 3;           // 0..3 (32 cols each)

    // per-lane ldmatrix offsets (within one operand tile)
    const int la = lane & 15;
    const uint32_t a_lane_off = (uint32_t)((wm * 64 + la) * (SROW * 2) + (lane >> 4) * 16);
    const uint32_t b_lane_off = (uint32_t)((wn * 32 + (la & 7)) * (SROW * 2) + ((la >> 3) & 1) * 16);

    float acc[4][4][4];
#pragma unroll
    for (int mi = 0; mi < 4; mi++)
#pragma unroll
        for (int ni = 0; ni < 4; ni++)
#pragma unroll
            for (int j = 0; j < 4; j++) acc[mi][ni][j] = 0.0f;

    stage_load(sbase, Ah, Al, Bh, Bl, 0, tid);
    cp_commit();

    for (int c = 0; c < 16; c++) {
        const uint32_t sb = sbase + (uint32_t)((c & 1) * STAGE_BYTES);
        if (c < 15) {
            stage_load(sbase + (uint32_t)(((c + 1) & 1) * STAGE_BYTES),
                       Ah, Al, Bh, Bl, (c + 1) * BK, tid);
            cp_commit();
            cp_wait<1>();
        } else {
            cp_wait<0>();
        }
        __syncthreads();

#pragma unroll
        for (int kk = 0; kk < 2; kk++) {
            uint32_t ah[4][4], al2[4][4], bh[4][2], bl2[4][2];
#pragma unroll
            for (int mi = 0; mi < 4; mi++) {
                uint32_t ad = sb + a_lane_off + (uint32_t)(mi * 16 * (SROW * 2) + kk * 32);
                ldsm4(ah[mi], ad);
                ldsm4(al2[mi], ad + MAT_BYTES);
            }
#pragma unroll
            for (int ni = 0; ni < 4; ni++) {
                uint32_t bd = sb + 2 * MAT_BYTES + b_lane_off +
                              (uint32_t)(ni * 8 * (SROW * 2) + kk * 32);
                ldsm2(bh[ni], bd);
                ldsm2(bl2[ni], bd + MAT_BYTES);
            }
#pragma unroll
            for (int mi = 0; mi < 4; mi++)
#pragma unroll
                for (int ni = 0; ni < 4; ni++) {
                    mma16816(acc[mi][ni], ah[mi], bh[ni]);
                    mma16816(acc[mi][ni], ah[mi], bl2[ni]);
                    mma16816(acc[mi][ni], al2[mi], bh[ni]);
                }
        }
        __syncthreads();
    }

    // epilogue: c0,c1 -> (r, col..col+1), c2,c3 -> (r+8, col..col+1)
    const int r0 = lane >> 2;
    const int c0 = (lane & 3) * 2;
#pragma unroll
    for (int mi = 0; mi < 4; mi++) {
#pragma unroll
        for (int ni = 0; ni < 4; ni++) {
            int row = wm * 64 + mi * 16 + r0;
            int col = wn * 32 + ni * 8 + c0;
            float2 v0 = make_float2(acc[mi][ni][0], acc[mi][ni][1]);
            float2 v1 = make_float2(acc[mi][ni][2], acc[mi][ni][3]);
            if (bias) {
                float b0 = bias[col], b1 = bias[col + 1];
                v0.x += b0; v0.y += b1; v1.x += b0; v1.y += b1;
            }
            *(float2*)(C + (size_t)row * ldc + col) = v0;
            *(float2*)(C + (size_t)(row + 8) * ldc + col) = v1;
        }
    }
}

__global__ __launch_bounds__(256) void gemm_qkv_tc(void) {
    const size_t bm = (size_t)blockIdx.y * 128, bn = (size_t)blockIdx.x * 128;
    tc_gemm(g_xh + bm * 512, g_xl + bm * 512,
            g_wh + bn * 512, g_wl + bn * 512,
            nullptr, g_qkv + bm * QKV_COLS + bn, QKV_COLS);
}

__global__ __launch_bounds__(256) void gemm_out_tc(const float* __restrict__ bout,
                                                   float* __restrict__ out) {
    const int b = blockIdx.z;
    const size_t arow = (size_t)b * SEQ + (size_t)blockIdx.y * 128;
    const size_t brow = (size_t)b * DIM + (size_t)blockIdx.x * 128;
    tc_gemm(g_qh + arow * 512, g_ql + arow * 512,
            g_mh + brow * 512, g_ml + brow * 512,
            bout + blockIdx.x * 128,
            out + arow * DIM + blockIdx.x * 128, DIM);
}

// ---------------------------------------------------------------------------
// bf16 hi/lo split kernels
// ---------------------------------------------------------------------------
__device__ __forceinline__ void split4(float4 v, __nv_bfloat16* hi, __nv_bfloat16* lo,
                                       size_t idx) {
    __nv_bfloat16 hx = __float2bfloat16(v.x), hy = __float2bfloat16(v.y);
    __nv_bfloat16 hz = __float2bfloat16(v.z), hw = __float2bfloat16(v.w);
    hi[idx + 0] = hx; hi[idx + 1] = hy; hi[idx + 2] = hz; hi[idx + 3] = hw;
    lo[idx + 0] = __float2bfloat16(v.x - __bfloat162float(hx));
    lo[idx + 1] = __float2bfloat16(v.y - __bfloat162float(hy));
    lo[idx + 2] = __float2bfloat16(v.z - __bfloat162float(hz));
    lo[idx + 3] = __float2bfloat16(v.w - __bfloat162float(hw));
}

__global__ __launch_bounds__(256) void split_kernel(const float* __restrict__ src,
                                                    __nv_bfloat16* __restrict__ hi,
                                                    __nv_bfloat16* __restrict__ lo,
                                                    int n4) {
    int i = blockIdx.x * 256 + threadIdx.x;
    if (i >= n4) return;
    split4(((const float4*)src)[i], hi, lo, (size_t)i * 4);
}

// q section of g_qkv (row stride 1536) -> packed q_hi/q_lo (row stride 512)
__global__ __launch_bounds__(256) void split_q_kernel(void) {
    int i = blockIdx.x * 256 + threadIdx.x;     // ROWS*128 float4s
    int row = i >> 7, c4 = i & 127;
    float4 v = *(const float4*)(g_qkv + (size_t)row * QKV_COLS + c4 * 4);
    split4(v, g_qh, g_ql, (size_t)row * 512 + c4 * 4);
}

// ---------------------------------------------------------------------------
// LN(k,v) + 2D RoPE(q,k) in-place on g_qkv. One warp per (b,n,h) row.
// ---------------------------------------------------------------------------
__device__ __forceinline__ float warp_sum(float v) {
#pragma unroll
    for (int o = 16; o > 0; o >>= 1) v += __shfl_xor_sync(0xffffffffu, v, o);
    return v;
}

__global__ __launch_bounds__(256) void ln_rope_kernel(const float* __restrict__ pos,
                                                      const float* __restrict__ gk,
                                                      const float* __restrict__ bk,
                                                      const float* __restrict__ gv,
                                                      const float* __restrict__ bv) {
    const int warp = threadIdx.x >> 5;
    const int lane = threadIdx.x & 31;
    const int r = blockIdx.x * 8 + warp;
    const int b = r >> 15;
    const int rem = r & 32767;
    const int n = rem >> 3;
    const int h = rem & 7;

    float* qp = g_qkv + ((size_t)(b * SEQ + n)) * QKV_COLS + h * DH;
    float* kp = qp + INNER;
    float* vp = qp + 2 * INNER;

    float q0 = qp[lane], q1 = qp[lane + 32];
    float k0 = kp[lane], k1 = kp[lane + 32];
    float v0 = vp[lane], v1 = vp[lane + 32];

    float mu = warp_sum(k0 + k1) * (1.0f / 64.0f);
    float d0 = k0 - mu, d1 = k1 - mu;
    float var = warp_sum(d0 * d0 + d1 * d1) * (1.0f / 64.0f);
    float inv = rsqrtf(var + EPS);
    k0 = d0 * inv * gk[lane] + bk[lane];
    k1 = d1 * inv * gk[lane + 32] + bk[lane + 32];

    mu = warp_sum(v0 + v1) * (1.0f / 64.0f);
    d0 = v0 - mu; d1 = v1 - mu;
    var = warp_sum(d0 * d0 + d1 * d1) * (1.0f / 64.0f);
    inv = rsqrtf(var + EPS);
    v0 = d0 * inv * gv[lane] + bv[lane];
    v1 = d1 * inv * gv[lane + 32] + bv[lane + 32];

    const float cx = pos[((size_t)(b * SEQ + n)) * 2 + 0];
    const float cy = pos[((size_t)(b * SEQ + n)) * 2 + 1];
    float invf = exp2f(-0.830482023721841f * (float)(lane & 15));
    float sx, cxs, sy, cys;
    sincosf(cx * 64.0f * invf, &sx, &cxs);
    sincosf(cy * 64.0f * invf, &sy, &cys);
    const float sgn = (lane < 16) ? -1.0f : 1.0f;

    float qr0 = q0 * cxs + sgn * __shfl_xor_sync(0xffffffffu, q0, 16) * sx;
    float qr1 = q1 * cys + sgn * __shfl_xor_sync(0xffffffffu, q1, 16) * sy;
    float kr0 = k0 * cxs + sgn * __shfl_xor_sync(0xffffffffu, k0, 16) * sx;
    float kr1 = k1 * cys + sgn * __shfl_xor_sync(0xffffffffu, k1, 16) * sy;

    qp[lane] = qr0; qp[lane + 32] = qr1;
    kp[lane] = kr0; kp[lane + 32] = kr1;
    vp[lane] = v0;  vp[lane + 32] = v1;
}

// ---------------------------------------------------------------------------
// dots = K^T V (atomic accumulation over token chunks)
// ---------------------------------------------------------------------------
__global__ void zero_dots_kernel() {
    g_dots[blockIdx.x * blockDim.x + threadIdx.x] = 0.0f;
}

__global__ __launch_bounds__(256) void kv_dots_kernel() {
    __shared__ __align__(16) float ks[8][64];
    __shared__ __align__(16) float vs[8][64];

    const int bh = blockIdx.x;
    const int b = bh >> 3, h = bh & 7;
    const int n0 = blockIdx.y * 256;
    const int tid = threadIdx.x;
    const int d0 = (tid >> 4) * 4;
    const int e0 = (tid & 15) * 4;

    float acc[4][4];
#pragma unroll
    for (int i = 0; i < 4; i++)
#pragma unroll
        for (int j = 0; j < 4; j++) acc[i][j] = 0.0f;

    for (int t0 = 0; t0 < 256; t0 += 8) {
        __syncthreads();
#pragma unroll
        for (int i = tid; i < 1024; i += 256) {
            int sel = i >> 9;
            int ii = i & 511;
            int tt = ii >> 6;
            int d = ii & 63;
            size_t row = ((size_t)(b * SEQ + n0 + t0 + tt)) * QKV_COLS + h * DH;
            float val = g_qkv[row + (sel ? 2 * INNER : INNER) + d];
            if (sel) vs[tt][d] = val; else ks[tt][d] = val;
        }
        __syncthreads();
#pragma unroll
        for (int tt = 0; tt < 8; tt++) {
            float4 kv = *(const float4*)&ks[tt][d0];
            float4 vv = *(const float4*)&vs[tt][e0];
            float ka[4] = {kv.x, kv.y, kv.z, kv.w};
            float va[4] = {vv.x, vv.y, vv.z, vv.w};
#pragma unroll
            for (int i = 0; i < 4; i++)
#pragma unroll
                for (int j = 0; j < 4; j++) acc[i][j] += ka[i] * va[j];
        }
    }

    float* dbase = g_dots + (size_t)bh * DH * DH;
#pragma unroll
    for (int i = 0; i < 4; i++)
#pragma unroll
        for (int j = 0; j < 4; j++)
            atomicAdd(&dbase[(d0 + i) * DH + (e0 + j)], acc[i][j]);
}

// ---------------------------------------------------------------------------
// McatT[b][o, h*64+d] = (1/SEQ) * sum_e dots[b,h,d,e] * Wout[o, h*64+e]
// written directly as bf16 hi/lo.  grid (64 bh, 8 o-chunks of 64)
// ---------------------------------------------------------------------------
__global__ __launch_bounds__(256) void mcat_kernel(const float* __restrict__ Wout) {
    __shared__ float ds[64][65];
    __shared__ float ws[64][65];

    const int bh = blockIdx.x;
    const int b = bh >> 3, h = bh & 7;
    const int o0 = blockIdx.y * 64;
    const int tid = threadIdx.x;

    for (int i = tid; i < 4096; i += 256) {
        int d = i >> 6, e = i & 63;
        ds[d][e] = g_dots[(size_t)bh * 4096 + i];
        ws[d][e] = Wout[(size_t)(o0 + d) * INNER + h * DH + e];
    }
    __syncthreads();

    for (int t = tid; t < 4096; t += 256) {
        int oL = t >> 6, d = t & 63;
        float acc = 0.0f;
#pragma unroll
        for (int e = 0; e < 64; e++) acc += ds[d][e] * ws[oL][e];
        acc *= (1.0f / (float)SEQ);
        size_t idx = ((size_t)b * DIM + (o0 + oL)) * 512 + h * DH + d;
        __nv_bfloat16 hi = __float2bfloat16(acc);
        g_mh[idx] = hi;
        g_ml[idx] = __float2bfloat16(acc - __bfloat162float(hi));
    }
}

// ---------------------------------------------------------------------------
// launch
// ---------------------------------------------------------------------------
extern "C" void kernel_launch(void* const* d_in, const int* in_sizes, int n_in,
                              void* d_out, int out_size) {
    const float* x    = (const float*)d_in[0];
    const float* pos  = (const float*)d_in[1];
    const float* Wqkv = (const float*)d_in[2];
    const float* gk   = (const float*)d_in[3];
    const float* bk   = (const float*)d_in[4];
    const float* gv   = (const float*)d_in[5];
    const float* bv   = (const float*)d_in[6];
    const float* Wout = (const float*)d_in[7];
    const float* bout = (const float*)d_in[8];
    float* out = (float*)d_out;

    static bool attr_done = false;
    if (!attr_done) {
        cudaFuncSetAttribute(gemm_qkv_tc, cudaFuncAttributeMaxDynamicSharedMemorySize, GEMM_SMEM);
        cudaFuncSetAttribute(gemm_out_tc, cudaFuncAttributeMaxDynamicSharedMemorySize, GEMM_SMEM);
        attr_done = true;
    }

    void* p_xh; void* p_xl; void* p_wh; void* p_wl;
    cudaGetSymbolAddress(&p_xh, g_xh); cudaGetSymbolAddress(&p_xl, g_xl);
    cudaGetSymbolAddress(&p_wh, g_wh); cudaGetSymbolAddress(&p_wl, g_wl);

    // 1) split x and Wqkv into bf16 hi/lo
    int n4x = (ROWS * DIM) / 4;
    split_kernel<<<(n4x + 255) / 256, 256>>>(x, (__nv_bfloat16*)p_xh,
                                             (__nv_bfloat16*)p_xl, n4x);
    int n4w = (QKV_COLS * DIM) / 4;
    split_kernel<<<(n4w + 255) / 256, 256>>>(Wqkv, (__nv_bfloat16*)p_wh,
                                             (__nv_bfloat16*)p_wl, n4w);

    // 2) qkv = x @ Wqkv^T (HMMA split-bf16) -> g_qkv fp32
    gemm_qkv_tc<<<dim3(QKV_COLS / 128, ROWS / 128), 256, GEMM_SMEM>>>();

    // 3) LN(k,v) + RoPE(q,k) in-place
    ln_rope_kernel<<<(BATCH * SEQ * HEADS) / 8, 256>>>(pos, gk, bk, gv, bv);

    // 4) dots = K^T V
    zero_dots_kernel<<<(BATCH * HEADS * DH * DH) / 256, 256>>>();
    kv_dots_kernel<<<dim3(BATCH * HEADS, SEQ / 256), 256>>>();

    // 5) McatT[b] = (dots[b] @ Wout^T)/SEQ  (bf16 hi/lo), and split q
    mcat_kernel<<<dim3(BATCH * HEADS, DIM / 64), 256>>>(Wout);
    split_q_kernel<<<(ROWS * INNER / 4) / 256, 256>>>();

    // 6) out[b] = q[b] @ McatT[b]^T + b_out  (HMMA split-bf16)
    gemm_out_tc<<<dim3(DIM / 128, SEQ / 128, BATCH), 256, GEMM_SMEM>>>(bout, out);
}